// round 10
// baseline (speedup 1.0000x reference)
#include <cuda_runtime.h>
#include <cuda_bf16.h>
#include <math.h>

#define BATCH 64
#define TLEN  512
#define DIM   512

#define NGRP   4
#define GBLKS  32
#define BPG    16
#define CPB    16
#define QRT    4      // k-quarters of 128

// -------- device scratch --------
__device__ float g_x[3][TLEN * BATCH * DIM];   // [gate][t][b][j]
__device__ float g_h[DIM * BATCH];             // [j][b]
__device__ float g_rh[DIM * BATCH];            // [j][b]
// [group][0=h,1=rh][quarter][pad to 128B]
__device__ unsigned int g_cnt[NGRP][2][QRT][32];

__device__ __forceinline__ unsigned int f2tf32(float x) {
    unsigned int r;
    asm("cvt.rna.tf32.f32 %0, %1;" : "=r"(r) : "f"(x));
    return r;
}

__device__ __forceinline__ void mma_tf32(float* c, unsigned int a0, unsigned int a1,
                                         unsigned int a2, unsigned int a3,
                                         unsigned int b0, unsigned int b1) {
    asm volatile(
        "mma.sync.aligned.m16n8k8.row.col.f32.tf32.tf32.f32 "
        "{%0,%1,%2,%3}, {%4,%5,%6,%7}, {%8,%9}, {%0,%1,%2,%3};"
        : "+f"(c[0]), "+f"(c[1]), "+f"(c[2]), "+f"(c[3])
        : "r"(a0), "r"(a1), "r"(a2), "r"(a3), "r"(b0), "r"(b1));
}

__device__ __forceinline__ unsigned long long pk2(float x, float y) {
    unsigned long long r;
    asm("mov.b64 %0, {%1, %2};" : "=l"(r) : "f"(x), "f"(y));
    return r;
}
__device__ __forceinline__ void fma2(unsigned long long& c, unsigned long long a,
                                     unsigned long long b) {
    asm("fma.rn.f32x2 %0, %1, %2, %0;" : "+l"(c) : "l"(a), "l"(b));
}

// =================================================================
// Phase 1: input projections via tf32 tensor cores (unchanged)
// =================================================================
#define PAS 20
#define PBS 136

__global__ __launch_bounds__(256) void proj_kernel(
    const float* __restrict__ X,
    const float* __restrict__ Wz, const float* __restrict__ Wr, const float* __restrict__ Wh,
    const float* __restrict__ bz, const float* __restrict__ br, const float* __restrict__ bh)
{
    __shared__ float As[128 * PAS];
    __shared__ float Bs[16 * PBS];

    if (blockIdx.x == 0 && blockIdx.y == 0 && blockIdx.z == 0) {
        for (int i = threadIdx.x; i < NGRP * 2 * QRT * 32; i += 256)
            ((unsigned int*)g_cnt)[i] = 0u;
    }

    const int mat = blockIdx.z;
    const float* W    = (mat == 0) ? Wz : ((mat == 1) ? Wr : Wh);
    const float* bias = (mat == 0) ? bz : ((mat == 1) ? br : bh);
    float* dst = &g_x[mat][0];

    const int m0 = blockIdx.y * 128;
    const int n0 = blockIdx.x * 128;
    const int tid = threadIdx.x;
    const int wid = tid >> 5;
    const int wm = wid >> 2;
    const int wn = wid & 3;
    const int lane = tid & 31;
    const int g = lane >> 2;
    const int q = lane & 3;

    float acc[4][4][4];
#pragma unroll
    for (int i = 0; i < 4; ++i)
#pragma unroll
        for (int j = 0; j < 4; ++j)
#pragma unroll
            for (int e = 0; e < 4; ++e) acc[i][j][e] = 0.f;

    const int xr = tid >> 2, xq = (tid & 3) * 4;
    const int wk = tid >> 5, wc = (tid & 31) * 4;

    for (int kt = 0; kt < 512; kt += 16) {
#pragma unroll
        for (int ii = 0; ii < 2; ++ii) {
            int r = xr + ii * 64;
            float4 v = *(const float4*)&X[(m0 + r) * 512 + kt + xq];
            As[r * PAS + xq + 0] = __uint_as_float(f2tf32(v.x));
            As[r * PAS + xq + 1] = __uint_as_float(f2tf32(v.y));
            As[r * PAS + xq + 2] = __uint_as_float(f2tf32(v.z));
            As[r * PAS + xq + 3] = __uint_as_float(f2tf32(v.w));
        }
#pragma unroll
        for (int ii = 0; ii < 2; ++ii) {
            int k = wk + ii * 8;
            float4 v = *(const float4*)&W[(kt + k) * 512 + n0 + wc];
            Bs[k * PBS + wc + 0] = __uint_as_float(f2tf32(v.x));
            Bs[k * PBS + wc + 1] = __uint_as_float(f2tf32(v.y));
            Bs[k * PBS + wc + 2] = __uint_as_float(f2tf32(v.z));
            Bs[k * PBS + wc + 3] = __uint_as_float(f2tf32(v.w));
        }
        __syncthreads();

#pragma unroll
        for (int k8 = 0; k8 < 16; k8 += 8) {
            unsigned int af[4][4];
#pragma unroll
            for (int mt = 0; mt < 4; ++mt) {
                int rb = wm * 64 + mt * 16;
                af[mt][0] = __float_as_uint(As[(rb + g) * PAS + k8 + q]);
                af[mt][1] = __float_as_uint(As[(rb + g + 8) * PAS + k8 + q]);
                af[mt][2] = __float_as_uint(As[(rb + g) * PAS + k8 + q + 4]);
                af[mt][3] = __float_as_uint(As[(rb + g + 8) * PAS + k8 + q + 4]);
            }
            unsigned int bf[4][2];
#pragma unroll
            for (int nt = 0; nt < 4; ++nt) {
                int nb = wn * 32 + nt * 8;
                bf[nt][0] = __float_as_uint(Bs[(k8 + q) * PBS + nb + g]);
                bf[nt][1] = __float_as_uint(Bs[(k8 + q + 4) * PBS + nb + g]);
            }
#pragma unroll
            for (int mt = 0; mt < 4; ++mt)
#pragma unroll
                for (int nt = 0; nt < 4; ++nt)
                    mma_tf32(acc[mt][nt], af[mt][0], af[mt][1], af[mt][2], af[mt][3],
                             bf[nt][0], bf[nt][1]);
        }
        __syncthreads();
    }

#pragma unroll
    for (int nt = 0; nt < 4; ++nt) {
        int c = n0 + wn * 32 + nt * 8 + 2 * q;
        float b0v = bias[c], b1v = bias[c + 1];
#pragma unroll
        for (int mt = 0; mt < 4; ++mt) {
            int r0 = m0 + wm * 64 + mt * 16 + g;
            int r1 = r0 + 8;
            int t0 = r0 & 511, bb0 = r0 >> 9;
            int t1 = r1 & 511, bb1 = r1 >> 9;
            float2 o0 = make_float2(acc[mt][nt][0] + b0v, acc[mt][nt][1] + b1v);
            float2 o1 = make_float2(acc[mt][nt][2] + b0v, acc[mt][nt][3] + b1v);
            *(float2*)&dst[(t0 * 64 + bb0) * 512 + c] = o0;
            *(float2*)&dst[(t1 * 64 + bb1) * 512 + c] = o1;
        }
    }
}

// =================================================================
// Phase 2: persistent GRU, quarter-pipelined exchange, warp-private staging
// =================================================================
#define SM_HS   (512*16)
#define SM_RHS  (512*16)
#define SM_UZR  (512*36)
#define SM_UH   (512*18)
#define RSTR    38
#define SM_RED  (16*16*RSTR)
#define SM_ZS   (16*16)
#define SMEM_FLOATS (SM_HS + SM_RHS + SM_UZR + SM_UH + SM_RED + SM_ZS + 32)

__global__ __launch_bounds__(256) void gru_kernel(
    const float* __restrict__ Uz, const float* __restrict__ Ur, const float* __restrict__ Uh,
    const int* __restrict__ mask, float* __restrict__ out)
{
    extern __shared__ float sm[];
    float* h_s   = sm;
    float* rh_s  = h_s + SM_HS;
    float* Uzr_s = rh_s + SM_RHS;
    float* Uh_s  = Uzr_s + SM_UZR;
    float* red   = Uh_s + SM_UH;
    float* z_s   = red + SM_RED;
    int*   m_s   = (int*)(z_s + SM_ZS);

    const int tid  = threadIdx.x;
    const int w    = tid >> 5;
    const int lane = tid & 31;
    const int bx   = blockIdx.x;
    const int bg   = bx >> 5;
    const int jg   = bx & 31;
    const int jb   = jg * CPB;
    const int b_base = bg * BPG;
    const int myq  = jg >> 3;          // quarter this block produces

    for (int i = tid; i < 512 * 16; i += 256) {
        int k = i >> 4, c = i & 15;
        Uzr_s[k * 36 + c]      = Uz[k * 512 + jb + c];
        Uzr_s[k * 36 + 16 + c] = Ur[k * 512 + jb + c];
        Uh_s [k * 18 + c]      = Uh[k * 512 + jb + c];
    }

    // zero own h cols (16 rows x 16 batches), then announce
    g_h[(jb + (tid >> 4)) * 64 + b_base + (tid & 15)] = 0.f;
    __syncthreads();
    if (tid == 0) { __threadfence(); atomicAdd(&g_cnt[bg][0][myq][0], 1u); }

    const int chunk = tid >> 4;        // = 2w + (lane>>4)
    const int sub   = tid & 15;
    const int b0    = (sub >> 3) * 8;
    const int c0A   = (sub & 7) * 4;
    const int c0B   = (sub & 7) * 2;

    const int bl0  = tid & 15;
    const int cz   = tid >> 4;
    const int btE  = bl0 >> 3;
    const int bhat = bl0 & 7;

    // warp staging geometry: 2 float4s per lane per quarter
    const int rl0 = lane >> 2;                 // 0..7
    const int rl1 = rl0 + 8;                   // 8..15
    const int c4  = (lane & 3) << 2;
    // row_local rl -> k = 2w + (rl>>3) + 16*(8q + (rl&7))

    for (int t = 0; t < TLEN; ++t) {
        const unsigned int tgt = 8u * (unsigned)(t + 1);

        // =================== Phase A: z and r ===================
        float xz = g_x[0][t * 32768 + (b_base + bl0) * 512 + jb + cz];
        float xr = g_x[1][t * 32768 + (b_base + bl0) * 512 + jb + cz];

        unsigned long long accp[4][4];
#pragma unroll
        for (int p = 0; p < 4; ++p)
#pragma unroll
            for (int c = 0; c < 4; ++c) accp[p][c] = 0ULL;

        {
            // double-buffered quarter pipeline
            float4 v0a, v0b;
            { // spin + load q0
                volatile unsigned int* hc = &g_cnt[bg][0][0][0];
                while (*hc < tgt) { }
                int k0 = 2 * w + 16 * (rl0 & 7);
                int k1 = 2 * w + 1 + 16 * (rl1 & 7);
                v0a = __ldcg((const float4*)(g_h + k0 * 64 + b_base + c4));
                v0b = __ldcg((const float4*)(g_h + k1 * 64 + b_base + c4));
            }
            for (int q = 0; q < 4; ++q) {
                float4 v1a, v1b;
                if (q < 3) {
                    volatile unsigned int* hc = &g_cnt[bg][0][q + 1][0];
                    while (*hc < tgt) { }
                    int k0 = 2 * w + 16 * (8 * (q + 1) + (rl0 & 7));
                    int k1 = 2 * w + 1 + 16 * (8 * (q + 1) + (rl1 & 7));
                    v1a = __ldcg((const float4*)(g_h + k0 * 64 + b_base + c4));
                    v1b = __ldcg((const float4*)(g_h + k1 * 64 + b_base + c4));
                }
                {
                    int k0 = 2 * w + 16 * (8 * q + (rl0 & 7));
                    int k1 = 2 * w + 1 + 16 * (8 * q + (rl1 & 7));
                    *(float4*)&h_s[k0 * 16 + c4] = v0a;
                    *(float4*)&h_s[k1 * 16 + c4] = v0b;
                }
                __syncwarp();
#pragma unroll
                for (int sl = 0; sl < 8; ++sl) {
                    int k = chunk + ((8 * q + sl) << 4);
                    ulonglong2 ha = *(const ulonglong2*)(h_s + k * 16 + b0);
                    ulonglong2 hb = *(const ulonglong2*)(h_s + k * 16 + b0 + 4);
                    float4 uv = *(const float4*)&Uzr_s[k * 36 + c0A];
                    unsigned long long u0 = pk2(uv.x, uv.x);
                    unsigned long long u1 = pk2(uv.y, uv.y);
                    unsigned long long u2 = pk2(uv.z, uv.z);
                    unsigned long long u3 = pk2(uv.w, uv.w);
                    unsigned long long hp[4] = {ha.x, ha.y, hb.x, hb.y};
#pragma unroll
                    for (int p = 0; p < 4; ++p) {
                        fma2(accp[p][0], hp[p], u0);
                        fma2(accp[p][1], hp[p], u1);
                        fma2(accp[p][2], hp[p], u2);
                        fma2(accp[p][3], hp[p], u3);
                    }
                }
                v0a = v1a; v0b = v1b;
                __syncwarp();
            }
        }

        {
            int slot = (chunk * 16 + sub) * RSTR;
#pragma unroll
            for (int p = 0; p < 4; ++p)
#pragma unroll
                for (int c = 0; c < 4; ++c)
                    *(unsigned long long*)&red[slot + c * 8 + 2 * p] = accp[p][c];
        }
        __syncthreads();

        {
            float s0 = 0.f, s1 = 0.f;
#pragma unroll
            for (int c = 0; c < 16; ++c) {
                s0 += red[(c * 16 + btE * 8 + (cz >> 2)) * RSTR + (cz & 3) * 8 + bhat];
                s1 += red[(c * 16 + btE * 8 + 4 + (cz >> 2)) * RSTR + (cz & 3) * 8 + bhat];
            }
            float zg = 1.f / (1.f + __expf(-(xz + s0)));
            z_s[cz * 16 + bl0] = zg;
            int jglob = jb + cz;
            float rg = 1.f / (1.f + __expf(-(xr + s1)));
            g_rh[jglob * 64 + b_base + bl0] = rg * h_s[jglob * 16 + bl0];
        }
        __syncthreads();
        if (tid == 0) { __threadfence(); atomicAdd(&g_cnt[bg][1][myq][0], 1u); }

        // =================== Phase B: candidate + update ===================
        float xh = g_x[2][t * 32768 + (b_base + bl0) * 512 + jb + cz];
        if (tid < 16) m_s[tid] = mask[(b_base + tid) * 512 + t];

        unsigned long long acc2p[4][2];
#pragma unroll
        for (int p = 0; p < 4; ++p) { acc2p[p][0] = 0ULL; acc2p[p][1] = 0ULL; }

        {
            float4 v0a, v0b;
            {
                volatile unsigned int* rc = &g_cnt[bg][1][0][0];
                while (*rc < tgt) { }
                int k0 = 2 * w + 16 * (rl0 & 7);
                int k1 = 2 * w + 1 + 16 * (rl1 & 7);
                v0a = __ldcg((const float4*)(g_rh + k0 * 64 + b_base + c4));
                v0b = __ldcg((const float4*)(g_rh + k1 * 64 + b_base + c4));
            }
            for (int q = 0; q < 4; ++q) {
                float4 v1a, v1b;
                if (q < 3) {
                    volatile unsigned int* rc = &g_cnt[bg][1][q + 1][0];
                    while (*rc < tgt) { }
                    int k0 = 2 * w + 16 * (8 * (q + 1) + (rl0 & 7));
                    int k1 = 2 * w + 1 + 16 * (8 * (q + 1) + (rl1 & 7));
                    v1a = __ldcg((const float4*)(g_rh + k0 * 64 + b_base + c4));
                    v1b = __ldcg((const float4*)(g_rh + k1 * 64 + b_base + c4));
                }
                {
                    int k0 = 2 * w + 16 * (8 * q + (rl0 & 7));
                    int k1 = 2 * w + 1 + 16 * (8 * q + (rl1 & 7));
                    *(float4*)&rh_s[k0 * 16 + c4] = v0a;
                    *(float4*)&rh_s[k1 * 16 + c4] = v0b;
                }
                __syncwarp();
#pragma unroll
                for (int sl = 0; sl < 8; ++sl) {
                    int k = chunk + ((8 * q + sl) << 4);
                    ulonglong2 ra = *(const ulonglong2*)(rh_s + k * 16 + b0);
                    ulonglong2 rb = *(const ulonglong2*)(rh_s + k * 16 + b0 + 4);
                    float2 uv = *(const float2*)&Uh_s[k * 18 + c0B];
                    unsigned long long u0 = pk2(uv.x, uv.x);
                    unsigned long long u1 = pk2(uv.y, uv.y);
                    unsigned long long rp[4] = {ra.x, ra.y, rb.x, rb.y};
#pragma unroll
                    for (int p = 0; p < 4; ++p) {
                        fma2(acc2p[p][0], rp[p], u0);
                        fma2(acc2p[p][1], rp[p], u1);
                    }
                }
                v0a = v1a; v0b = v1b;
                __syncwarp();
            }
        }

        {
            int slot = (chunk * 16 + sub) * RSTR;
#pragma unroll
            for (int p = 0; p < 4; ++p) {
                *(unsigned long long*)&red[slot + 0 * 8 + 2 * p] = acc2p[p][0];
                *(unsigned long long*)&red[slot + 1 * 8 + 2 * p] = acc2p[p][1];
            }
        }
        __syncthreads();

        {
            float s2 = 0.f;
#pragma unroll
            for (int c = 0; c < 16; ++c)
                s2 += red[(c * 16 + btE * 8 + (cz >> 1)) * RSTR + (cz & 1) * 8 + bhat];
            float hh = tanhf(xh + s2);
            float zg = z_s[cz * 16 + bl0];
            int jglob = jb + cz;
            float hold = h_s[jglob * 16 + bl0];
            float hn   = zg * hold + (1.f - zg) * hh;
            float res  = (m_s[bl0] > 0) ? hn : hold;
            g_h[jglob * 64 + b_base + bl0] = res;
            if (t == TLEN - 1) out[(b_base + bl0) * 512 + jglob] = res;
        }
        __syncthreads();
        if (tid == 0) { __threadfence(); atomicAdd(&g_cnt[bg][0][myq][0], 1u); }
    }
}

// =================================================================
extern "C" void kernel_launch(void* const* d_in, const int* in_sizes, int n_in,
                              void* d_out, int out_size) {
    (void)in_sizes; (void)n_in; (void)out_size;
    const float* X    = (const float*)d_in[0];
    const int*   mask = (const int*)  d_in[1];
    const float* Wz   = (const float*)d_in[2];
    const float* Uz   = (const float*)d_in[3];
    const float* bz   = (const float*)d_in[4];
    const float* Wr   = (const float*)d_in[5];
    const float* Ur   = (const float*)d_in[6];
    const float* br   = (const float*)d_in[7];
    const float* Wh   = (const float*)d_in[8];
    const float* Uh   = (const float*)d_in[9];
    const float* bh   = (const float*)d_in[10];
    float* out = (float*)d_out;

    const int smem_bytes = SMEM_FLOATS * (int)sizeof(float);
    cudaFuncSetAttribute(gru_kernel, cudaFuncAttributeMaxDynamicSharedMemorySize, smem_bytes);

    proj_kernel<<<dim3(4, 256, 3), 256>>>(X, Wz, Wr, Wh, bz, br, bh);
    gru_kernel<<<128, 256, smem_bytes>>>(Uz, Ur, Uh, mask, out);
}

// round 11
// speedup vs baseline: 1.1337x; 1.1337x over previous
#include <cuda_runtime.h>
#include <cuda_bf16.h>
#include <math.h>

#define BATCH 64
#define TLEN  512
#define DIM   512

#define NGRP   4
#define GBLKS  32
#define BPG    16
#define CPB    16

// -------- device scratch --------
__device__ float g_x[3][TLEN * BATCH * DIM];   // [gate][t][b][j]
__device__ float g_h[DIM * BATCH];             // [j][b]
__device__ float g_rh[DIM * BATCH];            // [j][b]
__device__ unsigned int g_cnt[NGRP * 32];      // one counter per group, 128B apart

__device__ __forceinline__ unsigned int f2tf32(float x) {
    unsigned int r;
    asm("cvt.rna.tf32.f32 %0, %1;" : "=r"(r) : "f"(x));
    return r;
}

__device__ __forceinline__ void mma_tf32(float* c, unsigned int a0, unsigned int a1,
                                         unsigned int a2, unsigned int a3,
                                         unsigned int b0, unsigned int b1) {
    asm volatile(
        "mma.sync.aligned.m16n8k8.row.col.f32.tf32.tf32.f32 "
        "{%0,%1,%2,%3}, {%4,%5,%6,%7}, {%8,%9}, {%0,%1,%2,%3};"
        : "+f"(c[0]), "+f"(c[1]), "+f"(c[2]), "+f"(c[3])
        : "r"(a0), "r"(a1), "r"(a2), "r"(a3), "r"(b0), "r"(b1));
}

__device__ __forceinline__ unsigned long long pk2(float x, float y) {
    unsigned long long r;
    asm("mov.b64 %0, {%1, %2};" : "=l"(r) : "f"(x), "f"(y));
    return r;
}
__device__ __forceinline__ void fma2(unsigned long long& c, unsigned long long a,
                                     unsigned long long b) {
    asm("fma.rn.f32x2 %0, %1, %2, %0;" : "+l"(c) : "l"(a), "l"(b));
}

// =================================================================
// Phase 1: input projections via tf32 tensor cores (unchanged)
// =================================================================
#define PAS 20
#define PBS 136

__global__ __launch_bounds__(256) void proj_kernel(
    const float* __restrict__ X,
    const float* __restrict__ Wz, const float* __restrict__ Wr, const float* __restrict__ Wh,
    const float* __restrict__ bz, const float* __restrict__ br, const float* __restrict__ bh)
{
    __shared__ float As[128 * PAS];
    __shared__ float Bs[16 * PBS];

    if (blockIdx.x == 0 && blockIdx.y == 0 && blockIdx.z == 0 && threadIdx.x < NGRP * 32)
        g_cnt[threadIdx.x] = 0u;

    const int mat = blockIdx.z;
    const float* W    = (mat == 0) ? Wz : ((mat == 1) ? Wr : Wh);
    const float* bias = (mat == 0) ? bz : ((mat == 1) ? br : bh);
    float* dst = &g_x[mat][0];

    const int m0 = blockIdx.y * 128;
    const int n0 = blockIdx.x * 128;
    const int tid = threadIdx.x;
    const int wid = tid >> 5;
    const int wm = wid >> 2;
    const int wn = wid & 3;
    const int lane = tid & 31;
    const int g = lane >> 2;
    const int q = lane & 3;

    float acc[4][4][4];
#pragma unroll
    for (int i = 0; i < 4; ++i)
#pragma unroll
        for (int j = 0; j < 4; ++j)
#pragma unroll
            for (int e = 0; e < 4; ++e) acc[i][j][e] = 0.f;

    const int xr = tid >> 2, xq = (tid & 3) * 4;
    const int wk = tid >> 5, wc = (tid & 31) * 4;

    for (int kt = 0; kt < 512; kt += 16) {
#pragma unroll
        for (int ii = 0; ii < 2; ++ii) {
            int r = xr + ii * 64;
            float4 v = *(const float4*)&X[(m0 + r) * 512 + kt + xq];
            As[r * PAS + xq + 0] = __uint_as_float(f2tf32(v.x));
            As[r * PAS + xq + 1] = __uint_as_float(f2tf32(v.y));
            As[r * PAS + xq + 2] = __uint_as_float(f2tf32(v.z));
            As[r * PAS + xq + 3] = __uint_as_float(f2tf32(v.w));
        }
#pragma unroll
        for (int ii = 0; ii < 2; ++ii) {
            int k = wk + ii * 8;
            float4 v = *(const float4*)&W[(kt + k) * 512 + n0 + wc];
            Bs[k * PBS + wc + 0] = __uint_as_float(f2tf32(v.x));
            Bs[k * PBS + wc + 1] = __uint_as_float(f2tf32(v.y));
            Bs[k * PBS + wc + 2] = __uint_as_float(f2tf32(v.z));
            Bs[k * PBS + wc + 3] = __uint_as_float(f2tf32(v.w));
        }
        __syncthreads();

#pragma unroll
        for (int k8 = 0; k8 < 16; k8 += 8) {
            unsigned int af[4][4];
#pragma unroll
            for (int mt = 0; mt < 4; ++mt) {
                int rb = wm * 64 + mt * 16;
                af[mt][0] = __float_as_uint(As[(rb + g) * PAS + k8 + q]);
                af[mt][1] = __float_as_uint(As[(rb + g + 8) * PAS + k8 + q]);
                af[mt][2] = __float_as_uint(As[(rb + g) * PAS + k8 + q + 4]);
                af[mt][3] = __float_as_uint(As[(rb + g + 8) * PAS + k8 + q + 4]);
            }
            unsigned int bf[4][2];
#pragma unroll
            for (int nt = 0; nt < 4; ++nt) {
                int nb = wn * 32 + nt * 8;
                bf[nt][0] = __float_as_uint(Bs[(k8 + q) * PBS + nb + g]);
                bf[nt][1] = __float_as_uint(Bs[(k8 + q + 4) * PBS + nb + g]);
            }
#pragma unroll
            for (int mt = 0; mt < 4; ++mt)
#pragma unroll
                for (int nt = 0; nt < 4; ++nt)
                    mma_tf32(acc[mt][nt], af[mt][0], af[mt][1], af[mt][2], af[mt][3],
                             bf[nt][0], bf[nt][1]);
        }
        __syncthreads();
    }

#pragma unroll
    for (int nt = 0; nt < 4; ++nt) {
        int c = n0 + wn * 32 + nt * 8 + 2 * q;
        float b0v = bias[c], b1v = bias[c + 1];
#pragma unroll
        for (int mt = 0; mt < 4; ++mt) {
            int r0 = m0 + wm * 64 + mt * 16 + g;
            int r1 = r0 + 8;
            int t0 = r0 & 511, bb0 = r0 >> 9;
            int t1 = r1 & 511, bb1 = r1 >> 9;
            float2 o0 = make_float2(acc[mt][nt][0] + b0v, acc[mt][nt][1] + b1v);
            float2 o1 = make_float2(acc[mt][nt][2] + b0v, acc[mt][nt][3] + b1v);
            *(float2*)&dst[(t0 * 64 + bb0) * 512 + c] = o0;
            *(float2*)&dst[(t1 * 64 + bb1) * 512 + c] = o1;
        }
    }
}

// =================================================================
// Phase 2: persistent GRU (R9 structure + tid0 fence + prefetch rotation)
// =================================================================
#define SM_HS   (512*16)
#define SM_RHS  (512*16)
#define SM_UZR  (512*36)
#define SM_UH   (512*18)
#define RSTR    38
#define SM_RED  (16*16*RSTR)
#define SM_ZS   (16*16)
#define SMEM_FLOATS (SM_HS + SM_RHS + SM_UZR + SM_UH + SM_RED + SM_ZS + 32)

// sync-first release barrier: all writes ordered before tid0's fence via bar.sync
__device__ __forceinline__ void group_barrier(unsigned int* cnt, unsigned int target) {
    __syncthreads();
    if (threadIdx.x == 0) {
        __threadfence();
        atomicAdd(cnt, 1u);
        while (*((volatile unsigned int*)cnt) < target) { }
    }
    __syncthreads();
}

__global__ __launch_bounds__(256) void gru_kernel(
    const float* __restrict__ Uz, const float* __restrict__ Ur, const float* __restrict__ Uh,
    const int* __restrict__ mask, float* __restrict__ out)
{
    extern __shared__ float sm[];
    float* h_s   = sm;
    float* rh_s  = h_s + SM_HS;
    float* Uzr_s = rh_s + SM_RHS;
    float* Uh_s  = Uzr_s + SM_UZR;
    float* red   = Uh_s + SM_UH;
    float* z_s   = red + SM_RED;

    const int tid = threadIdx.x;
    const int bx  = blockIdx.x;
    const int bg  = bx >> 5;
    const int jg  = bx & 31;
    const int jb  = jg * CPB;
    const int b_base = bg * BPG;
    unsigned int* cnt = &g_cnt[bg * 32];

    for (int i = tid; i < 512 * 16; i += 256) {
        int k = i >> 4, c = i & 15;
        Uzr_s[k * 36 + c]      = Uz[k * 512 + jb + c];
        Uzr_s[k * 36 + 16 + c] = Ur[k * 512 + jb + c];
        Uh_s [k * 18 + c]      = Uh[k * 512 + jb + c];
    }

    g_h[bx * 256 + tid] = 0.f;

    unsigned int round = 0;
    group_barrier(cnt, ++round * GBLKS);

    const int chunk = tid >> 4;
    const int sub   = tid & 15;
    const int b0    = (sub >> 3) * 8;
    const int c0A   = (sub & 7) * 4;
    const int c0B   = (sub & 7) * 2;

    const int bl0  = tid & 15;
    const int cz   = tid >> 4;
    const int btE  = bl0 >> 3;
    const int bhat = bl0 & 7;

    const float* xzp = &g_x[0][(b_base + bl0) * 512 + jb + cz];
    const float* xrp = &g_x[1][(b_base + bl0) * 512 + jb + cz];
    const float* xhp = &g_x[2][(b_base + bl0) * 512 + jb + cz];
    const int*   mp  = &mask[(b_base + bl0) * 512];

    // prologue prefetch for t = 0
    float xz = xzp[0];
    float xr = xrp[0];

    for (int t = 0; t < TLEN; ++t) {
        // =================== Phase A: z and r ===================
        // prefetch phase-B inputs for this step (in flight during A)
        float xh   = xhp[t * 32768];
        int   mreg = mp[t];

#pragma unroll 2
        for (int i = tid; i < 2048; i += 256) {
            int j = i >> 2, bq = (i & 3) << 2;
            float4 v = __ldcg((const float4*)(g_h + j * 64 + b_base + bq));
            *(float4*)&h_s[j * 16 + bq] = v;
        }
        __syncthreads();

        unsigned long long accp[4][4];
#pragma unroll
        for (int p = 0; p < 4; ++p)
#pragma unroll
            for (int c = 0; c < 4; ++c) accp[p][c] = 0ULL;

#pragma unroll 4
        for (int s = 0; s < 32; ++s) {
            int k = chunk + (s << 4);
            ulonglong2 ha = *(const ulonglong2*)(h_s + k * 16 + b0);
            ulonglong2 hb = *(const ulonglong2*)(h_s + k * 16 + b0 + 4);
            float4 uv = *(const float4*)&Uzr_s[k * 36 + c0A];
            unsigned long long u0 = pk2(uv.x, uv.x);
            unsigned long long u1 = pk2(uv.y, uv.y);
            unsigned long long u2 = pk2(uv.z, uv.z);
            unsigned long long u3 = pk2(uv.w, uv.w);
            unsigned long long hp[4] = {ha.x, ha.y, hb.x, hb.y};
#pragma unroll
            for (int p = 0; p < 4; ++p) {
                fma2(accp[p][0], hp[p], u0);
                fma2(accp[p][1], hp[p], u1);
                fma2(accp[p][2], hp[p], u2);
                fma2(accp[p][3], hp[p], u3);
            }
        }

        {
            int slot = (chunk * 16 + sub) * RSTR;
#pragma unroll
            for (int p = 0; p < 4; ++p)
#pragma unroll
                for (int c = 0; c < 4; ++c)
                    *(unsigned long long*)&red[slot + c * 8 + 2 * p] = accp[p][c];
        }
        __syncthreads();

        {
            float s0 = 0.f, s1 = 0.f;
#pragma unroll
            for (int c = 0; c < 16; ++c) {
                s0 += red[(c * 16 + btE * 8 + (cz >> 2)) * RSTR + (cz & 3) * 8 + bhat];
                s1 += red[(c * 16 + btE * 8 + 4 + (cz >> 2)) * RSTR + (cz & 3) * 8 + bhat];
            }
            float zg = 1.f / (1.f + __expf(-(xz + s0)));
            z_s[cz * 16 + bl0] = zg;
            int jglob = jb + cz;
            float rg = 1.f / (1.f + __expf(-(xr + s1)));
            g_rh[jglob * 64 + b_base + bl0] = rg * h_s[jglob * 16 + bl0];
        }
        group_barrier(cnt, ++round * GBLKS);

        // =================== Phase B: candidate + update ===================
        // prefetch phase-A inputs for t+1 (in flight during B and the barrier)
        if (t + 1 < TLEN) {
            xz = xzp[(t + 1) * 32768];
            xr = xrp[(t + 1) * 32768];
        }

#pragma unroll 2
        for (int i = tid; i < 2048; i += 256) {
            int j = i >> 2, bq = (i & 3) << 2;
            float4 v = __ldcg((const float4*)(g_rh + j * 64 + b_base + bq));
            *(float4*)&rh_s[j * 16 + bq] = v;
        }
        __syncthreads();

        unsigned long long acc2p[4][2];
#pragma unroll
        for (int p = 0; p < 4; ++p) { acc2p[p][0] = 0ULL; acc2p[p][1] = 0ULL; }

#pragma unroll 4
        for (int s = 0; s < 32; ++s) {
            int k = chunk + (s << 4);
            ulonglong2 ra = *(const ulonglong2*)(rh_s + k * 16 + b0);
            ulonglong2 rb = *(const ulonglong2*)(rh_s + k * 16 + b0 + 4);
            float2 uv = *(const float2*)&Uh_s[k * 18 + c0B];
            unsigned long long u0 = pk2(uv.x, uv.x);
            unsigned long long u1 = pk2(uv.y, uv.y);
            unsigned long long rp[4] = {ra.x, ra.y, rb.x, rb.y};
#pragma unroll
            for (int p = 0; p < 4; ++p) {
                fma2(acc2p[p][0], rp[p], u0);
                fma2(acc2p[p][1], rp[p], u1);
            }
        }

        {
            int slot = (chunk * 16 + sub) * RSTR;
#pragma unroll
            for (int p = 0; p < 4; ++p) {
                *(unsigned long long*)&red[slot + 0 * 8 + 2 * p] = acc2p[p][0];
                *(unsigned long long*)&red[slot + 1 * 8 + 2 * p] = acc2p[p][1];
            }
        }
        __syncthreads();

        {
            float s2 = 0.f;
#pragma unroll
            for (int c = 0; c < 16; ++c)
                s2 += red[(c * 16 + btE * 8 + (cz >> 1)) * RSTR + (cz & 1) * 8 + bhat];
            float hh = tanhf(xh + s2);
            float zg = z_s[cz * 16 + bl0];
            int jglob = jb + cz;
            float hold = h_s[jglob * 16 + bl0];
            float hn   = zg * hold + (1.f - zg) * hh;
            float res  = (mreg > 0) ? hn : hold;
            g_h[jglob * 64 + b_base + bl0] = res;
            if (t == TLEN - 1) out[(b_base + bl0) * 512 + jglob] = res;
        }
        group_barrier(cnt, ++round * GBLKS);
    }
}

// =================================================================
extern "C" void kernel_launch(void* const* d_in, const int* in_sizes, int n_in,
                              void* d_out, int out_size) {
    (void)in_sizes; (void)n_in; (void)out_size;
    const float* X    = (const float*)d_in[0];
    const int*   mask = (const int*)  d_in[1];
    const float* Wz   = (const float*)d_in[2];
    const float* Uz   = (const float*)d_in[3];
    const float* bz   = (const float*)d_in[4];
    const float* Wr   = (const float*)d_in[5];
    const float* Ur   = (const float*)d_in[6];
    const float* br   = (const float*)d_in[7];
    const float* Wh   = (const float*)d_in[8];
    const float* Uh   = (const float*)d_in[9];
    const float* bh   = (const float*)d_in[10];
    float* out = (float*)d_out;

    const int smem_bytes = SMEM_FLOATS * (int)sizeof(float);
    cudaFuncSetAttribute(gru_kernel, cudaFuncAttributeMaxDynamicSharedMemorySize, smem_bytes);

    proj_kernel<<<dim3(4, 256, 3), 256>>>(X, Wz, Wr, Wh, bz, br, bh);
    gru_kernel<<<128, 256, smem_bytes>>>(Uz, Ur, Uh, mask, out);
}